// round 3
// baseline (speedup 1.0000x reference)
#include <cuda_runtime.h>

// ---------------- problem constants ----------------
#define BATCH 2
#define S     2048
#define DM    1024
#define H     16
#define HD    64
#define TDM   3072          // 3*DM
#define FFN   4096
#define TOK   4096          // BATCH*S
#define EPS   1e-5f

// ---------------- scratch (static __device__, allocation-free) ----------------
__device__ float g_qkv[(size_t)TOK * TDM];                 // 50 MB
__device__ float g_scores[(size_t)BATCH * H * S * S];      // 537 MB
__device__ float g_ctx[(size_t)TOK * DM];                  // 16.8 MB
__device__ float g_tmp[(size_t)TOK * DM];                  // attn_out+x, then ffn2+h
__device__ float g_h[(size_t)TOK * DM];                    // post-LN1
__device__ float g_ffn[(size_t)TOK * FFN];                 // 67 MB

// ---------------- generic NN GEMM: C = A[MxK] @ B[KxN] (+bias)(+resid)(relu?) --------
// Tiles: 128x128x16, 256 threads, 8x8 per thread. All dims are multiples (no guards).
__global__ __launch_bounds__(256)
void gemm_kernel(const float* __restrict__ A, const float* __restrict__ B,
                 const float* __restrict__ bias, const float* __restrict__ resid,
                 float* __restrict__ C, int M, int N, int K, int relu)
{
    __shared__ float As[16][132];   // [k][m], padded to dodge STS conflicts
    __shared__ float Bs[16][128];   // [k][n]

    const int tid  = threadIdx.x;
    const int bx   = blockIdx.x, by = blockIdx.y;
    const float* Ab = A + (size_t)by * 128 * K;
    const float* Bb = B + (size_t)bx * 128;
    const int trow = tid >> 4;      // 0..15
    const int tcol = tid & 15;      // 0..15

    float acc[8][8];
#pragma unroll
    for (int i = 0; i < 8; i++)
#pragma unroll
        for (int j = 0; j < 8; j++) acc[i][j] = 0.f;

    for (int k0 = 0; k0 < K; k0 += 16) {
#pragma unroll
        for (int t = 0; t < 2; t++) {
            int flat = tid + t * 256;          // 0..511
            int r = flat >> 2;                 // 0..127
            int c = (flat & 3) << 2;           // 0,4,8,12
            float4 v = *(const float4*)(Ab + (size_t)r * K + k0 + c);
            As[c + 0][r] = v.x; As[c + 1][r] = v.y;
            As[c + 2][r] = v.z; As[c + 3][r] = v.w;
        }
#pragma unroll
        for (int t = 0; t < 2; t++) {
            int flat = tid + t * 256;
            int r = flat >> 5;                 // 0..15
            int c = (flat & 31) << 2;          // 0..124
            *(float4*)(&Bs[r][c]) = *(const float4*)(Bb + (size_t)(k0 + r) * N + c);
        }
        __syncthreads();

#pragma unroll
        for (int k = 0; k < 16; k++) {
            float a[8], b[8];
            *(float4*)(a)     = *(float4*)(&As[k][trow * 8]);
            *(float4*)(a + 4) = *(float4*)(&As[k][trow * 8 + 4]);
            *(float4*)(b)     = *(float4*)(&Bs[k][tcol * 8]);
            *(float4*)(b + 4) = *(float4*)(&Bs[k][tcol * 8 + 4]);
#pragma unroll
            for (int i = 0; i < 8; i++)
#pragma unroll
                for (int j = 0; j < 8; j++) acc[i][j] += a[i] * b[j];
        }
        __syncthreads();
    }

#pragma unroll
    for (int i = 0; i < 8; i++) {
        int row = by * 128 + trow * 8 + i;
#pragma unroll
        for (int j = 0; j < 8; j += 4) {
            int col = bx * 128 + tcol * 8 + j;
            float4 v = make_float4(acc[i][j], acc[i][j+1], acc[i][j+2], acc[i][j+3]);
            if (bias) {
                float4 bb = *(const float4*)(bias + col);
                v.x += bb.x; v.y += bb.y; v.z += bb.z; v.w += bb.w;
            }
            if (resid) {
                float4 rr = *(const float4*)(resid + (size_t)row * N + col);
                v.x += rr.x; v.y += rr.y; v.z += rr.z; v.w += rr.w;
            }
            if (relu) {
                v.x = fmaxf(v.x, 0.f); v.y = fmaxf(v.y, 0.f);
                v.z = fmaxf(v.z, 0.f); v.w = fmaxf(v.w, 0.f);
            }
            *(float4*)(C + (size_t)row * N + col) = v;
        }
    }
}

// ------------- scores[z,i,j] = (1/8) * dot(q_i, k_j), per z=b*H+h ----------------
// Block tile 128(i) x 64(j), K=64 single pass. 256 threads, 8x4 per thread.
__global__ __launch_bounds__(256)
void scores_kernel(const float* __restrict__ qkv, float* __restrict__ scores)
{
    const int z  = blockIdx.z;
    const int b  = z >> 4, h = z & 15;
    const int i0 = blockIdx.y * 128;
    const int j0 = blockIdx.x * 64;

    __shared__ float Qs[128][65];
    __shared__ float Ks[64][65];

    const int tid = threadIdx.x;
    const float* qb = qkv + (size_t)b * S * TDM + h * 192;

#pragma unroll
    for (int t = 0; t < 8; t++) {              // 128x64 Q tile
        int flat = tid + t * 256;              // 0..2047
        int r = flat >> 4;                     // 0..127
        int c = (flat & 15) << 2;              // 0..60
        float4 v = *(const float4*)(qb + (size_t)(i0 + r) * TDM + c);
        Qs[r][c] = v.x; Qs[r][c+1] = v.y; Qs[r][c+2] = v.z; Qs[r][c+3] = v.w;
    }
#pragma unroll
    for (int t = 0; t < 4; t++) {              // 64x64 K tile
        int flat = tid + t * 256;              // 0..1023
        int r = flat >> 4;                     // 0..63
        int c = (flat & 15) << 2;
        float4 v = *(const float4*)(qb + 64 + (size_t)(j0 + r) * TDM + c);
        Ks[r][c] = v.x; Ks[r][c+1] = v.y; Ks[r][c+2] = v.z; Ks[r][c+3] = v.w;
    }
    __syncthreads();

    const int tx = tid & 15;                   // 16 col groups (4 cols each)
    const int ty = tid >> 4;                   // 16 row groups (8 rows each)
    float acc[8][4];
#pragma unroll
    for (int i = 0; i < 8; i++)
#pragma unroll
        for (int j = 0; j < 4; j++) acc[i][j] = 0.f;

#pragma unroll 16
    for (int k = 0; k < 64; k++) {
        float a[8], bb[4];
#pragma unroll
        for (int i = 0; i < 8; i++) a[i] = Qs[ty * 8 + i][k];
#pragma unroll
        for (int j = 0; j < 4; j++) bb[j] = Ks[tx * 4 + j][k];
#pragma unroll
        for (int i = 0; i < 8; i++)
#pragma unroll
            for (int j = 0; j < 4; j++) acc[i][j] += a[i] * bb[j];
    }

    float* out = scores + (size_t)z * S * S;
#pragma unroll
    for (int i = 0; i < 8; i++) {
        int row = i0 + ty * 8 + i;
        float4 v = make_float4(acc[i][0] * 0.125f, acc[i][1] * 0.125f,
                               acc[i][2] * 0.125f, acc[i][3] * 0.125f);
        *(float4*)(out + (size_t)row * S + j0 + tx * 4) = v;
    }
}

// ------------------------- row softmax over 2048 entries -------------------------
__global__ __launch_bounds__(256)
void softmax_kernel(float* __restrict__ scores)
{
    __shared__ float red[256];
    const size_t row = blockIdx.x;
    float* p = scores + row * (size_t)S;
    const int tid = threadIdx.x;

    float4 v0 = *(float4*)(p + tid * 4);
    float4 v1 = *(float4*)(p + 1024 + tid * 4);

    float m = fmaxf(fmaxf(fmaxf(v0.x, v0.y), fmaxf(v0.z, v0.w)),
                    fmaxf(fmaxf(v1.x, v1.y), fmaxf(v1.z, v1.w)));
    red[tid] = m; __syncthreads();
    for (int s = 128; s > 0; s >>= 1) {
        if (tid < s) red[tid] = fmaxf(red[tid], red[tid + s]);
        __syncthreads();
    }
    m = red[0];
    __syncthreads();

    v0.x = __expf(v0.x - m); v0.y = __expf(v0.y - m);
    v0.z = __expf(v0.z - m); v0.w = __expf(v0.w - m);
    v1.x = __expf(v1.x - m); v1.y = __expf(v1.y - m);
    v1.z = __expf(v1.z - m); v1.w = __expf(v1.w - m);
    float s8 = v0.x + v0.y + v0.z + v0.w + v1.x + v1.y + v1.z + v1.w;
    red[tid] = s8; __syncthreads();
    for (int s = 128; s > 0; s >>= 1) {
        if (tid < s) red[tid] += red[tid + s];
        __syncthreads();
    }
    float inv = 1.f / red[0];

    v0.x *= inv; v0.y *= inv; v0.z *= inv; v0.w *= inv;
    v1.x *= inv; v1.y *= inv; v1.z *= inv; v1.w *= inv;
    *(float4*)(p + tid * 4) = v0;
    *(float4*)(p + 1024 + tid * 4) = v1;
}

// ---------- ctx[b*S+i, h*64+d] = sum_j attn[z,i,j] * v[z,j,d] ----------
// Block tile 128(i) x 64(d), K-tile 16. 256 threads, 8x4 per thread.
__global__ __launch_bounds__(256)
void ctx_kernel(const float* __restrict__ scores, const float* __restrict__ qkv,
                float* __restrict__ ctx)
{
    const int z  = blockIdx.z;
    const int b  = z >> 4, h = z & 15;
    const int i0 = blockIdx.y * 128;

    __shared__ float As[16][132];   // [k][i]
    __shared__ float Bs[16][64];    // [k][d]

    const float* Ab = scores + (size_t)z * S * S + (size_t)i0 * S;
    const float* Vb = qkv + (size_t)b * S * TDM + h * 192 + 128;

    const int tid  = threadIdx.x;
    const int trow = tid >> 4;      // 0..15
    const int tcol = tid & 15;      // 0..15

    float acc[8][4];
#pragma unroll
    for (int i = 0; i < 8; i++)
#pragma unroll
        for (int j = 0; j < 4; j++) acc[i][j] = 0.f;

    for (int k0 = 0; k0 < S; k0 += 16) {
#pragma unroll
        for (int t = 0; t < 2; t++) {          // A: 128x16
            int flat = tid + t * 256;
            int r = flat >> 2;                 // 0..127
            int c = (flat & 3) << 2;
            float4 v = *(const float4*)(Ab + (size_t)r * S + k0 + c);
            As[c + 0][r] = v.x; As[c + 1][r] = v.y;
            As[c + 2][r] = v.z; As[c + 3][r] = v.w;
        }
        {                                      // B: 16x64
            int r = tid >> 4;                  // 0..15
            int c = (tid & 15) << 2;           // 0..60
            *(float4*)(&Bs[r][c]) = *(const float4*)(Vb + (size_t)(k0 + r) * TDM + c);
        }
        __syncthreads();

#pragma unroll
        for (int k = 0; k < 16; k++) {
            float a[8], bb[4];
            *(float4*)(a)     = *(float4*)(&As[k][trow * 8]);
            *(float4*)(a + 4) = *(float4*)(&As[k][trow * 8 + 4]);
            *(float4*)(bb)    = *(float4*)(&Bs[k][tcol * 4]);
#pragma unroll
            for (int i = 0; i < 8; i++)
#pragma unroll
                for (int j = 0; j < 4; j++) acc[i][j] += a[i] * bb[j];
        }
        __syncthreads();
    }

#pragma unroll
    for (int i = 0; i < 8; i++) {
        int row = i0 + trow * 8 + i;
        float4 v = make_float4(acc[i][0], acc[i][1], acc[i][2], acc[i][3]);
        *(float4*)(ctx + ((size_t)(b * S + row)) * DM + h * 64 + tcol * 4) = v;
    }
}

// ------------------------- LayerNorm over rows of 1024 -------------------------
__global__ __launch_bounds__(256)
void ln_kernel(const float* __restrict__ x, const float* __restrict__ gamma,
               const float* __restrict__ beta, float* __restrict__ out)
{
    __shared__ float r1[256];
    __shared__ float r2[256];
    const size_t row = blockIdx.x;
    const float* p = x + row * DM;
    const int tid = threadIdx.x;

    float4 v = *(const float4*)(p + tid * 4);
    float s  = v.x + v.y + v.z + v.w;
    float s2 = v.x * v.x + v.y * v.y + v.z * v.z + v.w * v.w;
    r1[tid] = s; r2[tid] = s2; __syncthreads();
    for (int st = 128; st > 0; st >>= 1) {
        if (tid < st) { r1[tid] += r1[tid + st]; r2[tid] += r2[tid + st]; }
        __syncthreads();
    }
    float mean = r1[0] * (1.f / DM);
    float var  = r2[0] * (1.f / DM) - mean * mean;
    float inv  = rsqrtf(var + EPS);

    float4 g = *(const float4*)(gamma + tid * 4);
    float4 b = *(const float4*)(beta + tid * 4);
    float4 o;
    o.x = (v.x - mean) * inv * g.x + b.x;
    o.y = (v.y - mean) * inv * g.y + b.y;
    o.z = (v.z - mean) * inv * g.z + b.z;
    o.w = (v.w - mean) * inv * g.w + b.w;
    *(float4*)(out + row * DM + tid * 4) = o;
}

// ---------------------------------- launch ----------------------------------
extern "C" void kernel_launch(void* const* d_in, const int* in_sizes, int n_in,
                              void* d_out, int out_size)
{
    const float* x      = (const float*)d_in[0];
    const float* W_qkv  = (const float*)d_in[1];
    const float* b_qkv  = (const float*)d_in[2];
    const float* W_o    = (const float*)d_in[3];
    const float* b_o    = (const float*)d_in[4];
    const float* gamma1 = (const float*)d_in[5];
    const float* beta1  = (const float*)d_in[6];
    const float* W1     = (const float*)d_in[7];
    const float* b1     = (const float*)d_in[8];
    const float* W2     = (const float*)d_in[9];
    const float* b2     = (const float*)d_in[10];
    const float* gamma2 = (const float*)d_in[11];
    const float* beta2  = (const float*)d_in[12];
    float* out = (float*)d_out;

    float *qkv, *scores, *ctx, *tmp, *h, *ffn;
    cudaGetSymbolAddress((void**)&qkv,    g_qkv);
    cudaGetSymbolAddress((void**)&scores, g_scores);
    cudaGetSymbolAddress((void**)&ctx,    g_ctx);
    cudaGetSymbolAddress((void**)&tmp,    g_tmp);
    cudaGetSymbolAddress((void**)&h,      g_h);
    cudaGetSymbolAddress((void**)&ffn,    g_ffn);

    // 1) qkv = x @ W_qkv + b_qkv
    gemm_kernel<<<dim3(TDM / 128, TOK / 128), 256>>>(x, W_qkv, b_qkv, nullptr,
                                                     qkv, TOK, TDM, DM, 0);
    // 2) scores = Q K^T / 8
    scores_kernel<<<dim3(S / 64, S / 128, BATCH * H), 256>>>(qkv, scores);
    // 3) softmax rows
    softmax_kernel<<<BATCH * H * S, 256>>>(scores);
    // 4) ctx = attn @ V (per head, merged into [TOK, DM])
    ctx_kernel<<<dim3(1, S / 128, BATCH * H), 256>>>(scores, qkv, ctx);
    // 5) tmp = ctx @ W_o + b_o + x
    gemm_kernel<<<dim3(DM / 128, TOK / 128), 256>>>(ctx, W_o, b_o, x,
                                                    tmp, TOK, DM, DM, 0);
    // 6) h = LN1(tmp)
    ln_kernel<<<TOK, 256>>>(tmp, gamma1, beta1, h);
    // 7) ffn = relu(h @ W1 + b1)
    gemm_kernel<<<dim3(FFN / 128, TOK / 128), 256>>>(h, W1, b1, nullptr,
                                                     ffn, TOK, FFN, DM, 1);
    // 8) tmp = ffn @ W2 + b2 + h
    gemm_kernel<<<dim3(DM / 128, TOK / 128), 256>>>(ffn, W2, b2, h,
                                                    tmp, TOK, DM, FFN, 0);
    // 9) out = LN2(tmp)
    ln_kernel<<<TOK, 256>>>(tmp, gamma2, beta2, out);
}

// round 6
// speedup vs baseline: 1.5956x; 1.5956x over previous
#include <cuda_runtime.h>
#include <cuda_bf16.h>
#include <cstdint>

// ---------------- problem constants ----------------
#define BATCH 2
#define S     2048
#define DM    1024
#define H     16
#define HD    64
#define TDM   3072          // 3*DM
#define FFN   4096
#define TOK   4096          // BATCH*S
#define EPS   1e-5f

// ---------------- scratch (static __device__, allocation-free) ----------------
__device__ float g_qkv[(size_t)TOK * TDM];                 // 50 MB
__device__ float g_scores[(size_t)BATCH * H * S * S];      // 537 MB
__device__ float g_ctx[(size_t)TOK * DM];
__device__ float g_tmp[(size_t)TOK * DM];
__device__ float g_h[(size_t)TOK * DM];

// bf16 hi/lo planes
__device__ __align__(16) __nv_bfloat16 g_wbf[25165824];    // all weights, 50 MB
#define WQKV_HI 0ull
#define WQKV_LO 3145728ull
#define WO_HI   6291456ull
#define WO_LO   7340032ull
#define W1_HI   8388608ull
#define W1_LO   12582912ull
#define W2_HI   16777216ull
#define W2_LO   20971520ull
__device__ __align__(16) __nv_bfloat16 g_xbf[8388608];     // x planes
__device__ __align__(16) __nv_bfloat16 g_ctxbf[8388608];
__device__ __align__(16) __nv_bfloat16 g_hbf[8388608];
__device__ __align__(16) __nv_bfloat16 g_ffnbf[33554432];  // ffn planes, 67 MB

// ======================= helpers =======================
__device__ __forceinline__ uint32_t smem_u32(const void* p) {
    uint32_t a;
    asm("{ .reg .u64 t; cvta.to.shared.u64 t, %1; cvt.u32.u64 %0, t; }" : "=r"(a) : "l"(p));
    return a;
}
#define CP_COMMIT() asm volatile("cp.async.commit_group;" ::: "memory")
#define CP_WAIT2()  asm volatile("cp.async.wait_group 2;" ::: "memory")

__device__ __forceinline__ void cp_async16(uint32_t dst, const void* src) {
    asm volatile("cp.async.ca.shared.global [%0], [%1], 16;"
                 :: "r"(dst), "l"(__cvta_generic_to_global(src)) : "memory");
}
__device__ __forceinline__ void ldsm_x4(uint32_t* r, uint32_t a) {
    asm volatile("ldmatrix.sync.aligned.m8n8.x4.shared.b16 {%0,%1,%2,%3}, [%4];"
                 : "=r"(r[0]), "=r"(r[1]), "=r"(r[2]), "=r"(r[3]) : "r"(a));
}
__device__ __forceinline__ void mma_bf16(float* c, const uint32_t* a, const uint32_t* b) {
    asm volatile(
        "mma.sync.aligned.m16n8k16.row.col.f32.bf16.bf16.f32 "
        "{%0,%1,%2,%3}, {%4,%5,%6,%7}, {%8,%9}, {%0,%1,%2,%3};"
        : "+f"(c[0]), "+f"(c[1]), "+f"(c[2]), "+f"(c[3])
        : "r"(a[0]), "r"(a[1]), "r"(a[2]), "r"(a[3]), "r"(b[0]), "r"(b[1]));
}
__device__ __forceinline__ void split_bf16(float v, __nv_bfloat16& hi, __nv_bfloat16& lo) {
    hi = __float2bfloat16(v);
    lo = __float2bfloat16(v - __bfloat162float(hi));
}

// ============== transpose + split: W[k][n] fp32 -> Whi/Wlo [n][k] bf16 ==============
__global__ __launch_bounds__(256)
void transpose_convert_kernel(const float* __restrict__ W, __nv_bfloat16* __restrict__ Whi,
                              __nv_bfloat16* __restrict__ Wlo, int K, int N)
{
    __shared__ float t[32][33];
    const int k0 = blockIdx.y * 32, n0 = blockIdx.x * 32;
    const int tx = threadIdx.x & 31, ty = threadIdx.x >> 5;   // 32 x 8
#pragma unroll
    for (int j = 0; j < 32; j += 8)
        t[ty + j][tx] = W[(size_t)(k0 + ty + j) * N + n0 + tx];
    __syncthreads();
#pragma unroll
    for (int j = 0; j < 32; j += 8) {
        float v = t[tx][ty + j];
        __nv_bfloat16 hi, lo; split_bf16(v, hi, lo);
        size_t o = (size_t)(n0 + ty + j) * K + k0 + tx;
        Whi[o] = hi; Wlo[o] = lo;
    }
}

// ============== elementwise split: in fp32 -> hi/lo bf16 planes ==============
__global__ __launch_bounds__(256)
void convert_kernel(const float* __restrict__ in, __nv_bfloat16* __restrict__ hi,
                    __nv_bfloat16* __restrict__ lo)
{
    size_t i = ((size_t)blockIdx.x * 256 + threadIdx.x) * 4;
    float4 v = *(const float4*)(in + i);
    __nv_bfloat162 h2a, h2b, l2a, l2b;
    split_bf16(v.x, h2a.x, l2a.x); split_bf16(v.y, h2a.y, l2a.y);
    split_bf16(v.z, h2b.x, l2b.x); split_bf16(v.w, h2b.y, l2b.y);
    *(__nv_bfloat162*)(hi + i)     = h2a;
    *(__nv_bfloat162*)(hi + i + 2) = h2b;
    *(__nv_bfloat162*)(lo + i)     = l2a;
    *(__nv_bfloat162*)(lo + i + 2) = l2b;
}

// ====================== HMMA bf16-split GEMM ======================
// C[M,N] = A[M,K] @ Bt[N,K]^T via 3-pass hi/lo split.
// CTA 128x128, 8 warps (64x32 each), K-chunk 32, 3-stage cp.async pipeline.
#define ROWB     80                        // smem bytes per 32-elem bf16 row (pad 8)
#define PLANE_SZ 10240                     // 128 rows * 80B
#define STAGE_SZ 40960                     // Ahi|Alo|Bhi|Blo
#define NSTAGE   3
#define MG_SMEM  (NSTAGE * STAGE_SZ)       // 122880

__device__ __forceinline__ void mg_load_stage(
    uint32_t sb, int stage, const __nv_bfloat16* Ah, const __nv_bfloat16* Al,
    const __nv_bfloat16* Bh, const __nv_bfloat16* Bl, int K, int k0, int tid)
{
    const uint32_t base = sb + stage * STAGE_SZ;
#pragma unroll
    for (int j = 0; j < 8; j++) {
        const int plane = j >> 1;                       // compile-time
        const int rem = ((j & 1) << 8) + tid;           // 0..511
        const int row = rem >> 2;
        const int g = rem & 3;
        const __nv_bfloat16* src =
            (plane == 0 ? Ah : plane == 1 ? Al : plane == 2 ? Bh : Bl)
            + (size_t)row * K + k0 + g * 8;
        cp_async16(base + plane * PLANE_SZ + row * ROWB + g * 16, src);
    }
}

__global__ __launch_bounds__(256)
void mma_gemm(const __nv_bfloat16* __restrict__ Ahi, const __nv_bfloat16* __restrict__ Alo,
              const __nv_bfloat16* __restrict__ Bhi, const __nv_bfloat16* __restrict__ Blo,
              const float* __restrict__ bias, const float* __restrict__ resid,
              float* __restrict__ C, __nv_bfloat16* __restrict__ Ohi,
              __nv_bfloat16* __restrict__ Olo, int M, int N, int K, int relu)
{
    extern __shared__ char smem[];
    const uint32_t sb = smem_u32(smem);
    const int tid = threadIdx.x;
    const int wid = tid >> 5, lane = tid & 31;
    const int wm = (wid >> 2) * 64;        // 0 or 64
    const int wn = (wid & 3) * 32;         // 0,32,64,96
    const int m0 = blockIdx.y * 128, n0 = blockIdx.x * 128;

    const __nv_bfloat16* Ah = Ahi + (size_t)m0 * K;
    const __nv_bfloat16* Al = Alo + (size_t)m0 * K;
    const __nv_bfloat16* Bh = Bhi + (size_t)n0 * K;
    const __nv_bfloat16* Bl = Blo + (size_t)n0 * K;
    const int NC = K >> 5;

    float acc[4][4][4];
#pragma unroll
    for (int a = 0; a < 4; a++)
#pragma unroll
        for (int b = 0; b < 4; b++)
#pragma unroll
            for (int c = 0; c < 4; c++) acc[a][b][c] = 0.f;

    mg_load_stage(sb, 0, Ah, Al, Bh, Bl, K, 0, tid);  CP_COMMIT();
    mg_load_stage(sb, 1, Ah, Al, Bh, Bl, K, 32, tid); CP_COMMIT();

    for (int c = 0; c < NC; c++) {
        if (c + 2 < NC)
            mg_load_stage(sb, (c + 2) % NSTAGE, Ah, Al, Bh, Bl, K, (c + 2) * 32, tid);
        CP_COMMIT();
        CP_WAIT2();
        __syncthreads();

        const uint32_t st = sb + (c % NSTAGE) * STAGE_SZ;
#pragma unroll
        for (int ks = 0; ks < 2; ks++) {
            uint32_t ah[4][4], al[4][4], bh[8], bl[8];
            const int arow = wm + (lane & 15);
            const uint32_t akoff = ks * 32 + (lane >> 4) * 16;
#pragma unroll
            for (int mi = 0; mi < 4; mi++) {
                uint32_t aaddr = st + (arow + mi * 16) * ROWB + akoff;
                ldsm_x4(ah[mi], aaddr);
                ldsm_x4(al[mi], aaddr + PLANE_SZ);
            }
            const int sub = lane >> 3;
            const int brow = (lane & 7);
            const uint32_t bkoff = ks * 32 + (sub & 1) * 16;
#pragma unroll
            for (int nb = 0; nb < 2; nb++) {
                // B stored [n][k] (col-major k x n): NON-trans ldmatrix gives the
                // m16n8k16 B fragment directly (k-pair per reg, n = lane/4).
                uint32_t baddr = st + 2 * PLANE_SZ
                               + (wn + (nb * 2 + (sub >> 1)) * 8 + brow) * ROWB + bkoff;
                ldsm_x4(&bh[nb * 4], baddr);
                ldsm_x4(&bl[nb * 4], baddr + PLANE_SZ);
            }
#pragma unroll
            for (int mi = 0; mi < 4; mi++)
#pragma unroll
                for (int ni = 0; ni < 4; ni++) {
                    mma_bf16(acc[mi][ni], ah[mi], &bh[ni * 2]);
                    mma_bf16(acc[mi][ni], ah[mi], &bl[ni * 2]);
                    mma_bf16(acc[mi][ni], al[mi], &bh[ni * 2]);
                }
        }
        __syncthreads();
    }

    // ---------------- epilogue ----------------
#pragma unroll
    for (int mi = 0; mi < 4; mi++) {
        const int r0 = m0 + wm + mi * 16 + (lane >> 2);
        const int r1 = r0 + 8;
#pragma unroll
        for (int ni = 0; ni < 4; ni++) {
            const int col = n0 + wn + ni * 8 + (lane & 3) * 2;
            float v0 = acc[mi][ni][0], v1 = acc[mi][ni][1];
            float v2 = acc[mi][ni][2], v3 = acc[mi][ni][3];
            if (bias) {
                float b0 = bias[col], b1 = bias[col + 1];
                v0 += b0; v1 += b1; v2 += b0; v3 += b1;
            }
            if (resid) {
                const float* p0 = resid + (size_t)r0 * N + col;
                const float* p1 = resid + (size_t)r1 * N + col;
                v0 += p0[0]; v1 += p0[1]; v2 += p1[0]; v3 += p1[1];
            }
            if (relu) {
                v0 = fmaxf(v0, 0.f); v1 = fmaxf(v1, 0.f);
                v2 = fmaxf(v2, 0.f); v3 = fmaxf(v3, 0.f);
            }
            if (C) {
                *(float2*)(C + (size_t)r0 * N + col) = make_float2(v0, v1);
                *(float2*)(C + (size_t)r1 * N + col) = make_float2(v2, v3);
            }
            if (Ohi) {
                __nv_bfloat162 h0, l0, h1, l1;
                split_bf16(v0, h0.x, l0.x); split_bf16(v1, h0.y, l0.y);
                split_bf16(v2, h1.x, l1.x); split_bf16(v3, h1.y, l1.y);
                *(__nv_bfloat162*)(Ohi + (size_t)r0 * N + col) = h0;
                *(__nv_bfloat162*)(Ohi + (size_t)r1 * N + col) = h1;
                *(__nv_bfloat162*)(Olo + (size_t)r0 * N + col) = l0;
                *(__nv_bfloat162*)(Olo + (size_t)r1 * N + col) = l1;
            }
        }
    }
}

// ------------- scores[z,i,j] = (1/8) * dot(q_i, k_j), per z=b*H+h ----------------
__global__ __launch_bounds__(256)
void scores_kernel(const float* __restrict__ qkv, float* __restrict__ scores)
{
    const int z  = blockIdx.z;
    const int b  = z >> 4, h = z & 15;
    const int i0 = blockIdx.y * 128;
    const int j0 = blockIdx.x * 64;

    __shared__ float Qs[128][65];
    __shared__ float Ks[64][65];

    const int tid = threadIdx.x;
    const float* qb = qkv + (size_t)b * S * TDM + h * 192;

#pragma unroll
    for (int t = 0; t < 8; t++) {
        int flat = tid + t * 256;
        int r = flat >> 4;
        int c = (flat & 15) << 2;
        float4 v = *(const float4*)(qb + (size_t)(i0 + r) * TDM + c);
        Qs[r][c] = v.x; Qs[r][c+1] = v.y; Qs[r][c+2] = v.z; Qs[r][c+3] = v.w;
    }
#pragma unroll
    for (int t = 0; t < 4; t++) {
        int flat = tid + t * 256;
        int r = flat >> 4;
        int c = (flat & 15) << 2;
        float4 v = *(const float4*)(qb + 64 + (size_t)(j0 + r) * TDM + c);
        Ks[r][c] = v.x; Ks[r][c+1] = v.y; Ks[r][c+2] = v.z; Ks[r][c+3] = v.w;
    }
    __syncthreads();

    const int tx = tid & 15;
    const int ty = tid >> 4;
    float acc[8][4];
#pragma unroll
    for (int i = 0; i < 8; i++)
#pragma unroll
        for (int j = 0; j < 4; j++) acc[i][j] = 0.f;

#pragma unroll 16
    for (int k = 0; k < 64; k++) {
        float a[8], bb[4];
#pragma unroll
        for (int i = 0; i < 8; i++) a[i] = Qs[ty * 8 + i][k];
#pragma unroll
        for (int j = 0; j < 4; j++) bb[j] = Ks[tx * 4 + j][k];
#pragma unroll
        for (int i = 0; i < 8; i++)
#pragma unroll
            for (int j = 0; j < 4; j++) acc[i][j] += a[i] * bb[j];
    }

    float* out = scores + (size_t)z * S * S;
#pragma unroll
    for (int i = 0; i < 8; i++) {
        int row = i0 + ty * 8 + i;
        float4 v = make_float4(acc[i][0] * 0.125f, acc[i][1] * 0.125f,
                               acc[i][2] * 0.125f, acc[i][3] * 0.125f);
        *(float4*)(out + (size_t)row * S + j0 + tx * 4) = v;
    }
}

// ------------------------- row softmax over 2048 entries -------------------------
__global__ __launch_bounds__(256)
void softmax_kernel(float* __restrict__ scores)
{
    __shared__ float red[256];
    const size_t row = blockIdx.x;
    float* p = scores + row * (size_t)S;
    const int tid = threadIdx.x;

    float4 v0 = *(float4*)(p + tid * 4);
    float4 v1 = *(float4*)(p + 1024 + tid * 4);

    float m = fmaxf(fmaxf(fmaxf(v0.x, v0.y), fmaxf(v0.z, v0.w)),
                    fmaxf(fmaxf(v1.x, v1.y), fmaxf(v1.z, v1.w)));
    red[tid] = m; __syncthreads();
    for (int s = 128; s > 0; s >>= 1) {
        if (tid < s) red[tid] = fmaxf(red[tid], red[tid + s]);
        __syncthreads();
    }
    m = red[0];
    __syncthreads();

    v0.x = __expf(v0.x - m); v0.y = __expf(v0.y - m);
    v0.z = __expf(v0.z - m); v0.w = __expf(v0.w - m);
    v1.x = __expf(v1.x - m); v1.y = __expf(v1.y - m);
    v1.z = __expf(v1.z - m); v1.w = __expf(v1.w - m);
    float s8 = v0.x + v0.y + v0.z + v0.w + v1.x + v1.y + v1.z + v1.w;
    red[tid] = s8; __syncthreads();
    for (int s = 128; s > 0; s >>= 1) {
        if (tid < s) red[tid] += red[tid + s];
        __syncthreads();
    }
    float inv = 1.f / red[0];

    v0.x *= inv; v0.y *= inv; v0.z *= inv; v0.w *= inv;
    v1.x *= inv; v1.y *= inv; v1.z *= inv; v1.w *= inv;
    *(float4*)(p + tid * 4) = v0;
    *(float4*)(p + 1024 + tid * 4) = v1;
}

// ---------- ctx[b*S+i, h*64+d] = sum_j attn[z,i,j] * v[z,j,d] ----------
__global__ __launch_bounds__(256)
void ctx_kernel(const float* __restrict__ scores, const float* __restrict__ qkv,
                float* __restrict__ ctx)
{
    const int z  = blockIdx.z;
    const int b  = z >> 4, h = z & 15;
    const int i0 = blockIdx.y * 128;

    __shared__ float As[16][132];
    __shared__ float Bs[16][64];

    const float* Ab = scores + (size_t)z * S * S + (size_t)i0 * S;
    const float* Vb = qkv + (size_t)b * S * TDM + h * 192 + 128;

    const int tid  = threadIdx.x;
    const int trow = tid >> 4;
    const int tcol = tid & 15;

    float acc[8][4];
#pragma unroll
    for (int i = 0; i < 8; i++)
#pragma unroll
        for (int j = 0; j < 4; j++) acc[i][j] = 0.f;

    for (int k0 = 0; k0 < S; k0 += 16) {
#pragma unroll
        for (int t = 0; t < 2; t++) {
            int flat = tid + t * 256;
            int r = flat >> 2;
            int c = (flat & 3) << 2;
            float4 v = *(const float4*)(Ab + (size_t)r * S + k0 + c);
            As[c + 0][r] = v.x; As[c + 1][r] = v.y;
            As[c + 2][r] = v.z; As[c + 3][r] = v.w;
        }
        {
            int r = tid >> 4;
            int c = (tid & 15) << 2;
            *(float4*)(&Bs[r][c]) = *(const float4*)(Vb + (size_t)(k0 + r) * TDM + c);
        }
        __syncthreads();

#pragma unroll
        for (int k = 0; k < 16; k++) {
            float a[8], bb[4];
            *(float4*)(a)     = *(float4*)(&As[k][trow * 8]);
            *(float4*)(a + 4) = *(float4*)(&As[k][trow * 8 + 4]);
            *(float4*)(bb)    = *(float4*)(&Bs[k][tcol * 4]);
#pragma unroll
            for (int i = 0; i < 8; i++)
#pragma unroll
                for (int j = 0; j < 4; j++) acc[i][j] += a[i] * bb[j];
        }
        __syncthreads();
    }

#pragma unroll
    for (int i = 0; i < 8; i++) {
        int row = i0 + trow * 8 + i;
        float4 v = make_float4(acc[i][0], acc[i][1], acc[i][2], acc[i][3]);
        *(float4*)(ctx + ((size_t)(b * S + row)) * DM + h * 64 + tcol * 4) = v;
    }
}

// --------------- LayerNorm over rows of 1024 (+ optional bf16 planes) ---------------
__global__ __launch_bounds__(256)
void ln_kernel(const float* __restrict__ x, const float* __restrict__ gamma,
               const float* __restrict__ beta, float* __restrict__ out,
               __nv_bfloat16* __restrict__ ohi, __nv_bfloat16* __restrict__ olo)
{
    __shared__ float r1[256];
    __shared__ float r2[256];
    const size_t row = blockIdx.x;
    const float* p = x + row * DM;
    const int tid = threadIdx.x;

    float4 v = *(const float4*)(p + tid * 4);
    float s  = v.x + v.y + v.z + v.w;
    float s2 = v.x * v.x + v.y * v.y + v.z * v.z + v.w * v.w;
    r1[tid] = s; r2[tid] = s2; __syncthreads();
    for (int st = 128; st > 0; st >>= 1) {
        if (tid < st) { r1[tid] += r1[tid + st]; r2[tid] += r2[tid + st]; }
        __syncthreads();
    }
    float mean = r1[0] * (1.f / DM);
    float var  = r2[0] * (1.f / DM) - mean * mean;
    float inv  = rsqrtf(var + EPS);

    float4 g = *(const float4*)(gamma + tid * 4);
    float4 b = *(const float4*)(beta + tid * 4);
    float4 o;
    o.x = (v.x - mean) * inv * g.x + b.x;
    o.y = (v.y - mean) * inv * g.y + b.y;
    o.z = (v.z - mean) * inv * g.z + b.z;
    o.w = (v.w - mean) * inv * g.w + b.w;
    *(float4*)(out + row * DM + tid * 4) = o;

    if (ohi) {
        __nv_bfloat162 h0, l0, h1, l1;
        split_bf16(o.x, h0.x, l0.x); split_bf16(o.y, h0.y, l0.y);
        split_bf16(o.z, h1.x, l1.x); split_bf16(o.w, h1.y, l1.y);
        size_t q = row * DM + tid * 4;
        *(__nv_bfloat162*)(ohi + q)     = h0;
        *(__nv_bfloat162*)(ohi + q + 2) = h1;
        *(__nv_bfloat162*)(olo + q)     = l0;
        *(__nv_bfloat162*)(olo + q + 2) = l1;
    }
}

// ---------------------------------- launch ----------------------------------
extern "C" void kernel_launch(void* const* d_in, const int* in_sizes, int n_in,
                              void* d_out, int out_size)
{
    const float* x      = (const float*)d_in[0];
    const float* W_qkv  = (const float*)d_in[1];
    const float* b_qkv  = (const float*)d_in[2];
    const float* W_o    = (const float*)d_in[3];
    const float* b_o    = (const float*)d_in[4];
    const float* gamma1 = (const float*)d_in[5];
    const float* beta1  = (const float*)d_in[6];
    const float* W1     = (const float*)d_in[7];
    const float* b1     = (const float*)d_in[8];
    const float* W2     = (const float*)d_in[9];
    const float* b2     = (const float*)d_in[10];
    const float* gamma2 = (const float*)d_in[11];
    const float* beta2  = (const float*)d_in[12];
    float* out = (float*)d_out;

    float *qkv, *scores, *ctx, *tmp, *hbuf;
    __nv_bfloat16 *wbf, *xbf, *ctxbf, *hbf, *ffnbf;
    cudaGetSymbolAddress((void**)&qkv,    g_qkv);
    cudaGetSymbolAddress((void**)&scores, g_scores);
    cudaGetSymbolAddress((void**)&ctx,    g_ctx);
    cudaGetSymbolAddress((void**)&tmp,    g_tmp);
    cudaGetSymbolAddress((void**)&hbuf,   g_h);
    cudaGetSymbolAddress((void**)&wbf,    g_wbf);
    cudaGetSymbolAddress((void**)&xbf,    g_xbf);
    cudaGetSymbolAddress((void**)&ctxbf,  g_ctxbf);
    cudaGetSymbolAddress((void**)&hbf,    g_hbf);
    cudaGetSymbolAddress((void**)&ffnbf,  g_ffnbf);

    cudaFuncSetAttribute(mma_gemm, cudaFuncAttributeMaxDynamicSharedMemorySize, MG_SMEM);

    // 0) weight transpose+split and activation split
    transpose_convert_kernel<<<dim3(TDM / 32, DM / 32), 256>>>(W_qkv, wbf + WQKV_HI, wbf + WQKV_LO, DM, TDM);
    transpose_convert_kernel<<<dim3(DM / 32, DM / 32), 256>>>(W_o, wbf + WO_HI, wbf + WO_LO, DM, DM);
    transpose_convert_kernel<<<dim3(FFN / 32, DM / 32), 256>>>(W1, wbf + W1_HI, wbf + W1_LO, DM, FFN);
    transpose_convert_kernel<<<dim3(DM / 32, FFN / 32), 256>>>(W2, wbf + W2_HI, wbf + W2_LO, FFN, DM);
    convert_kernel<<<(TOK * DM) / 1024, 256>>>(x, xbf, xbf + (size_t)TOK * DM);

    // 1) qkv = x @ W_qkv + b_qkv
    mma_gemm<<<dim3(TDM / 128, TOK / 128), 256, MG_SMEM>>>(
        xbf, xbf + (size_t)TOK * DM, wbf + WQKV_HI, wbf + WQKV_LO,
        b_qkv, nullptr, qkv, nullptr, nullptr, TOK, TDM, DM, 0);

    // 2-4) attention (fp32 SIMT)
    scores_kernel<<<dim3(S / 64, S / 128, BATCH * H), 256>>>(qkv, scores);
    softmax_kernel<<<BATCH * H * S, 256>>>(scores);
    ctx_kernel<<<dim3(1, S / 128, BATCH * H), 256>>>(scores, qkv, ctx);

    // 5) tmp = ctx @ W_o + b_o + x
    convert_kernel<<<(TOK * DM) / 1024, 256>>>(ctx, ctxbf, ctxbf + (size_t)TOK * DM);
    mma_gemm<<<dim3(DM / 128, TOK / 128), 256, MG_SMEM>>>(
        ctxbf, ctxbf + (size_t)TOK * DM, wbf + WO_HI, wbf + WO_LO,
        b_o, x, tmp, nullptr, nullptr, TOK, DM, DM, 0);

    // 6) h = LN1(tmp), also split planes
    ln_kernel<<<TOK, 256>>>(tmp, gamma1, beta1, hbuf, hbf, hbf + (size_t)TOK * DM);

    // 7) ffn = relu(h @ W1 + b1) -> bf16 planes only
    mma_gemm<<<dim3(FFN / 128, TOK / 128), 256, MG_SMEM>>>(
        hbf, hbf + (size_t)TOK * DM, wbf + W1_HI, wbf + W1_LO,
        b1, nullptr, nullptr, ffnbf, ffnbf + (size_t)TOK * FFN, TOK, FFN, DM, 1);

    // 8) tmp = ffn @ W2 + b2 + h
    mma_gemm<<<dim3(DM / 128, TOK / 128), 256, MG_SMEM>>>(
        ffnbf, ffnbf + (size_t)TOK * FFN, wbf + W2_HI, wbf + W2_LO,
        b2, hbuf, tmp, nullptr, nullptr, TOK, DM, FFN, 0);

    // 9) out = LN2(tmp)
    ln_kernel<<<TOK, 256>>>(tmp, gamma2, beta2, out, nullptr, nullptr);
}

// round 7
// speedup vs baseline: 2.4078x; 1.5090x over previous
#include <cuda_runtime.h>
#include <cuda_bf16.h>
#include <cstdint>

// ---------------- problem constants ----------------
#define BATCH 2
#define S     2048
#define DM    1024
#define H     16
#define HD    64
#define TDM   3072          // 3*DM
#define FFN   4096
#define TOK   4096          // BATCH*S
#define EPS   1e-5f

// ---------------- scratch (static __device__, allocation-free) ----------------
__device__ float g_tmp[(size_t)TOK * DM];
__device__ float g_h[(size_t)TOK * DM];

// bf16 hi/lo planes
__device__ __align__(16) __nv_bfloat16 g_wbf[25165824];    // all weights, 50 MB
#define WQKV_HI 0ull
#define WQKV_LO 3145728ull
#define WO_HI   6291456ull
#define WO_LO   7340032ull
#define W1_HI   8388608ull
#define W1_LO   12582912ull
#define W2_HI   16777216ull
#define W2_LO   20971520ull
__device__ __align__(16) __nv_bfloat16 g_xbf[8388608];     // x hi/lo planes
__device__ __align__(16) __nv_bfloat16 g_qkvbf[25165824];  // qkv hi/lo planes, 50 MB
__device__ __align__(16) __nv_bfloat16 g_ctxbf[8388608];
__device__ __align__(16) __nv_bfloat16 g_hbf[8388608];
__device__ __align__(16) __nv_bfloat16 g_ffnbf[33554432];  // ffn hi/lo planes, 67 MB

// ======================= helpers =======================
__device__ __forceinline__ uint32_t smem_u32(const void* p) {
    uint32_t a;
    asm("{ .reg .u64 t; cvta.to.shared.u64 t, %1; cvt.u32.u64 %0, t; }" : "=r"(a) : "l"(p));
    return a;
}
#define CP_COMMIT() asm volatile("cp.async.commit_group;" ::: "memory")
#define CP_WAIT2()  asm volatile("cp.async.wait_group 2;" ::: "memory")
#define CP_WAIT1()  asm volatile("cp.async.wait_group 1;" ::: "memory")

__device__ __forceinline__ void cp_async16(uint32_t dst, const void* src) {
    asm volatile("cp.async.ca.shared.global [%0], [%1], 16;"
                 :: "r"(dst), "l"(__cvta_generic_to_global(src)) : "memory");
}
__device__ __forceinline__ void ldsm_x4(uint32_t* r, uint32_t a) {
    asm volatile("ldmatrix.sync.aligned.m8n8.x4.shared.b16 {%0,%1,%2,%3}, [%4];"
                 : "=r"(r[0]), "=r"(r[1]), "=r"(r[2]), "=r"(r[3]) : "r"(a));
}
__device__ __forceinline__ void ldsm_x4t(uint32_t* r, uint32_t a) {
    asm volatile("ldmatrix.sync.aligned.m8n8.x4.trans.shared.b16 {%0,%1,%2,%3}, [%4];"
                 : "=r"(r[0]), "=r"(r[1]), "=r"(r[2]), "=r"(r[3]) : "r"(a));
}
__device__ __forceinline__ void mma_bf16(float* c, const uint32_t* a, const uint32_t* b) {
    asm volatile(
        "mma.sync.aligned.m16n8k16.row.col.f32.bf16.bf16.f32 "
        "{%0,%1,%2,%3}, {%4,%5,%6,%7}, {%8,%9}, {%0,%1,%2,%3};"
        : "+f"(c[0]), "+f"(c[1]), "+f"(c[2]), "+f"(c[3])
        : "r"(a[0]), "r"(a[1]), "r"(a[2]), "r"(a[3]), "r"(b[0]), "r"(b[1]));
}
__device__ __forceinline__ void split_bf16(float v, __nv_bfloat16& hi, __nv_bfloat16& lo) {
    hi = __float2bfloat16(v);
    lo = __float2bfloat16(v - __bfloat162float(hi));
}

// ============== transpose + split: W[k][n] fp32 -> Whi/Wlo [n][k] bf16 ==============
__global__ __launch_bounds__(256)
void transpose_convert_kernel(const float* __restrict__ W, __nv_bfloat16* __restrict__ Whi,
                              __nv_bfloat16* __restrict__ Wlo, int K, int N)
{
    __shared__ float t[32][33];
    const int k0 = blockIdx.y * 32, n0 = blockIdx.x * 32;
    const int tx = threadIdx.x & 31, ty = threadIdx.x >> 5;   // 32 x 8
#pragma unroll
    for (int j = 0; j < 32; j += 8)
        t[ty + j][tx] = W[(size_t)(k0 + ty + j) * N + n0 + tx];
    __syncthreads();
#pragma unroll
    for (int j = 0; j < 32; j += 8) {
        float v = t[tx][ty + j];
        __nv_bfloat16 hi, lo; split_bf16(v, hi, lo);
        size_t o = (size_t)(n0 + ty + j) * K + k0 + tx;
        Whi[o] = hi; Wlo[o] = lo;
    }
}

// ============== elementwise split: in fp32 -> hi/lo bf16 planes ==============
__global__ __launch_bounds__(256)
void convert_kernel(const float* __restrict__ in, __nv_bfloat16* __restrict__ hi,
                    __nv_bfloat16* __restrict__ lo)
{
    size_t i = ((size_t)blockIdx.x * 256 + threadIdx.x) * 4;
    float4 v = *(const float4*)(in + i);
    __nv_bfloat162 h2a, h2b, l2a, l2b;
    split_bf16(v.x, h2a.x, l2a.x); split_bf16(v.y, h2a.y, l2a.y);
    split_bf16(v.z, h2b.x, l2b.x); split_bf16(v.w, h2b.y, l2b.y);
    *(__nv_bfloat162*)(hi + i)     = h2a;
    *(__nv_bfloat162*)(hi + i + 2) = h2b;
    *(__nv_bfloat162*)(lo + i)     = l2a;
    *(__nv_bfloat162*)(lo + i + 2) = l2b;
}

// ====================== HMMA bf16-split GEMM ======================
#define ROWB     80
#define PLANE_SZ 10240
#define STAGE_SZ 40960
#define NSTAGE   3
#define MG_SMEM  (NSTAGE * STAGE_SZ)

__device__ __forceinline__ void mg_load_stage(
    uint32_t sb, int stage, const __nv_bfloat16* Ah, const __nv_bfloat16* Al,
    const __nv_bfloat16* Bh, const __nv_bfloat16* Bl, int K, int k0, int tid)
{
    const uint32_t base = sb + stage * STAGE_SZ;
#pragma unroll
    for (int j = 0; j < 8; j++) {
        const int plane = j >> 1;
        const int rem = ((j & 1) << 8) + tid;
        const int row = rem >> 2;
        const int g = rem & 3;
        const __nv_bfloat16* src =
            (plane == 0 ? Ah : plane == 1 ? Al : plane == 2 ? Bh : Bl)
            + (size_t)row * K + k0 + g * 8;
        cp_async16(base + plane * PLANE_SZ + row * ROWB + g * 16, src);
    }
}

__global__ __launch_bounds__(256)
void mma_gemm(const __nv_bfloat16* __restrict__ Ahi, const __nv_bfloat16* __restrict__ Alo,
              const __nv_bfloat16* __restrict__ Bhi, const __nv_bfloat16* __restrict__ Blo,
              const float* __restrict__ bias, const float* __restrict__ resid,
              float* __restrict__ C, __nv_bfloat16* __restrict__ Ohi,
              __nv_bfloat16* __restrict__ Olo, int M, int N, int K, int relu)
{
    extern __shared__ char smem[];
    const uint32_t sb = smem_u32(smem);
    const int tid = threadIdx.x;
    const int wid = tid >> 5, lane = tid & 31;
    const int wm = (wid >> 2) * 64;
    const int wn = (wid & 3) * 32;
    const int m0 = blockIdx.y * 128, n0 = blockIdx.x * 128;

    const __nv_bfloat16* Ah = Ahi + (size_t)m0 * K;
    const __nv_bfloat16* Al = Alo + (size_t)m0 * K;
    const __nv_bfloat16* Bh = Bhi + (size_t)n0 * K;
    const __nv_bfloat16* Bl = Blo + (size_t)n0 * K;
    const int NC = K >> 5;

    float acc[4][4][4];
#pragma unroll
    for (int a = 0; a < 4; a++)
#pragma unroll
        for (int b = 0; b < 4; b++)
#pragma unroll
            for (int c = 0; c < 4; c++) acc[a][b][c] = 0.f;

    mg_load_stage(sb, 0, Ah, Al, Bh, Bl, K, 0, tid);  CP_COMMIT();
    mg_load_stage(sb, 1, Ah, Al, Bh, Bl, K, 32, tid); CP_COMMIT();

    for (int c = 0; c < NC; c++) {
        if (c + 2 < NC)
            mg_load_stage(sb, (c + 2) % NSTAGE, Ah, Al, Bh, Bl, K, (c + 2) * 32, tid);
        CP_COMMIT();
        CP_WAIT2();
        __syncthreads();

        const uint32_t st = sb + (c % NSTAGE) * STAGE_SZ;
#pragma unroll
        for (int ks = 0; ks < 2; ks++) {
            uint32_t ah[4][4], al[4][4], bh[8], bl[8];
            const int arow = wm + (lane & 15);
            const uint32_t akoff = ks * 32 + (lane >> 4) * 16;
#pragma unroll
            for (int mi = 0; mi < 4; mi++) {
                uint32_t aaddr = st + (arow + mi * 16) * ROWB + akoff;
                ldsm_x4(ah[mi], aaddr);
                ldsm_x4(al[mi], aaddr + PLANE_SZ);
            }
            const int sub = lane >> 3;
            const int brow = (lane & 7);
            const uint32_t bkoff = ks * 32 + (sub & 1) * 16;
#pragma unroll
            for (int nb = 0; nb < 2; nb++) {
                uint32_t baddr = st + 2 * PLANE_SZ
                               + (wn + (nb * 2 + (sub >> 1)) * 8 + brow) * ROWB + bkoff;
                ldsm_x4(&bh[nb * 4], baddr);
                ldsm_x4(&bl[nb * 4], baddr + PLANE_SZ);
            }
#pragma unroll
            for (int mi = 0; mi < 4; mi++)
#pragma unroll
                for (int ni = 0; ni < 4; ni++) {
                    mma_bf16(acc[mi][ni], ah[mi], &bh[ni * 2]);
                    mma_bf16(acc[mi][ni], ah[mi], &bl[ni * 2]);
                    mma_bf16(acc[mi][ni], al[mi], &bh[ni * 2]);
                }
        }
        __syncthreads();
    }

#pragma unroll
    for (int mi = 0; mi < 4; mi++) {
        const int r0 = m0 + wm + mi * 16 + (lane >> 2);
        const int r1 = r0 + 8;
#pragma unroll
        for (int ni = 0; ni < 4; ni++) {
            const int col = n0 + wn + ni * 8 + (lane & 3) * 2;
            float v0 = acc[mi][ni][0], v1 = acc[mi][ni][1];
            float v2 = acc[mi][ni][2], v3 = acc[mi][ni][3];
            if (bias) {
                float b0 = bias[col], b1 = bias[col + 1];
                v0 += b0; v1 += b1; v2 += b0; v3 += b1;
            }
            if (resid) {
                const float* p0 = resid + (size_t)r0 * N + col;
                const float* p1 = resid + (size_t)r1 * N + col;
                v0 += p0[0]; v1 += p0[1]; v2 += p1[0]; v3 += p1[1];
            }
            if (relu) {
                v0 = fmaxf(v0, 0.f); v1 = fmaxf(v1, 0.f);
                v2 = fmaxf(v2, 0.f); v3 = fmaxf(v3, 0.f);
            }
            if (C) {
                *(float2*)(C + (size_t)r0 * N + col) = make_float2(v0, v1);
                *(float2*)(C + (size_t)r1 * N + col) = make_float2(v2, v3);
            }
            if (Ohi) {
                __nv_bfloat162 h0, l0, h1, l1;
                split_bf16(v0, h0.x, l0.x); split_bf16(v1, h0.y, l0.y);
                split_bf16(v2, h1.x, l1.x); split_bf16(v3, h1.y, l1.y);
                *(__nv_bfloat162*)(Ohi + (size_t)r0 * N + col) = h0;
                *(__nv_bfloat162*)(Ohi + (size_t)r1 * N + col) = h1;
                *(__nv_bfloat162*)(Olo + (size_t)r0 * N + col) = l0;
                *(__nv_bfloat162*)(Olo + (size_t)r1 * N + col) = l1;
            }
        }
    }
}

// ====================== fused flash attention ======================
// One CTA = one (b,h) x 128 query rows. 8 warps, warp w owns rows [16w,16w+16).
// Iterate 16 K/V tiles of 128 keys, 2-stage cp.async pipeline.
// Q,K: [row][hd] -> non-trans ldmatrix. V: [key][hd] -> trans ldmatrix (B operand).
#define ARB     144                      // smem row bytes (64 bf16 + 16 pad)
#define APLANE  (128 * ARB)              // 18432
#define AT_KV   (2 * APLANE)             // Q hi/lo before this
#define AT_STAGE (4 * APLANE)            // Khi|Klo|Vhi|Vlo
#define AT_SMEM (2 * APLANE + 2 * AT_STAGE)   // 184320

__device__ __forceinline__ void at_load_kv(
    uint32_t base, const __nv_bfloat16* khi, const __nv_bfloat16* klo,
    const __nv_bfloat16* vhi, const __nv_bfloat16* vlo, int tid)
{
#pragma unroll
    for (int j = 0; j < 16; j++) {
        int idx = tid + j * 256;               // 0..4095
        const int plane = j >> 2;              // compile-time: 4 planes x 1024
        int rem = ((j & 3) << 8) + tid;        // 0..1023
        int r = rem >> 3, c = rem & 7;
        const __nv_bfloat16* src =
            (plane == 0 ? khi : plane == 1 ? klo : plane == 2 ? vhi : vlo)
            + (size_t)r * TDM + c * 8;
        cp_async16(base + plane * APLANE + r * ARB + c * 16, src);
        (void)idx;
    }
}

__global__ __launch_bounds__(256)
void attn_kernel(const __nv_bfloat16* __restrict__ qkvhi,
                 const __nv_bfloat16* __restrict__ qkvlo,
                 __nv_bfloat16* __restrict__ ctxhi,
                 __nv_bfloat16* __restrict__ ctxlo)
{
    extern __shared__ char smem[];
    const uint32_t sb = smem_u32(smem);
    const int tid = threadIdx.x;
    const int wid = tid >> 5, lane = tid & 31;
    const int z = blockIdx.y;                  // b*H + h
    const int b = z >> 4, h = z & 15;
    const int i0 = blockIdx.x * 128;

    const size_t tok0 = (size_t)b * S;
    const __nv_bfloat16* qh_g = qkvhi + (tok0 + i0) * TDM + h * 192;
    const __nv_bfloat16* ql_g = qkvlo + (tok0 + i0) * TDM + h * 192;

    // ---- load Q tile (hi/lo) ----
#pragma unroll
    for (int j = 0; j < 8; j++) {
        const int plane = j >> 2;
        int rem = ((j & 3) << 8) + tid;
        int r = rem >> 3, c = rem & 7;
        const __nv_bfloat16* src = (plane == 0 ? qh_g : ql_g) + (size_t)r * TDM + c * 8;
        cp_async16(sb + plane * APLANE + r * ARB + c * 16, src);
    }
    // ---- prologue KV stages 0,1 ----
    {
        const __nv_bfloat16* kh = qkvhi + tok0 * TDM + h * 192 + 64;
        const __nv_bfloat16* kl = qkvlo + tok0 * TDM + h * 192 + 64;
        const __nv_bfloat16* vh = qkvhi + tok0 * TDM + h * 192 + 128;
        const __nv_bfloat16* vl = qkvlo + tok0 * TDM + h * 192 + 128;
        CP_COMMIT();   // group: Q
        at_load_kv(sb + AT_KV, kh, kl, vh, vl, tid); CP_COMMIT();
        at_load_kv(sb + AT_KV + AT_STAGE, kh + 128 * TDM, kl + 128 * TDM,
                   vh + 128 * TDM, vl + 128 * TDM, tid); CP_COMMIT();
    }

    float oacc[8][4];
#pragma unroll
    for (int i = 0; i < 8; i++)
#pragma unroll
        for (int j = 0; j < 4; j++) oacc[i][j] = 0.f;
    float m0 = -1e30f, m1 = -1e30f, l0 = 0.f, l1 = 0.f;

    const int sub = lane >> 3, brow = lane & 7;

    for (int it = 0; it < 16; it++) {
        CP_WAIT1();            // current stage (and Q on it=0) complete
        __syncthreads();
        const uint32_t sK = sb + AT_KV + (it & 1) * AT_STAGE;
        const uint32_t sV = sK + 2 * APLANE;

        // ---- S = Q @ K^T (fp32 acc, 3-pass hi/lo) ----
        float sacc[16][4];
#pragma unroll
        for (int i = 0; i < 16; i++)
#pragma unroll
            for (int j = 0; j < 4; j++) sacc[i][j] = 0.f;

#pragma unroll
        for (int kg = 0; kg < 4; kg++) {
            uint32_t qh[4], ql[4];
            uint32_t aaddr = sb + (wid * 16 + (lane & 15)) * ARB + kg * 32 + (lane >> 4) * 16;
            ldsm_x4(qh, aaddr);
            ldsm_x4(ql, aaddr + APLANE);
#pragma unroll
            for (int ntp = 0; ntp < 8; ntp++) {
                uint32_t kh[4], kl[4];
                uint32_t baddr = sK + (ntp * 16 + (sub >> 1) * 8 + brow) * ARB
                               + kg * 32 + (sub & 1) * 16;
                ldsm_x4(kh, baddr);
                ldsm_x4(kl, baddr + APLANE);
                mma_bf16(sacc[2 * ntp],     qh, &kh[0]);
                mma_bf16(sacc[2 * ntp],     qh, &kl[0]);
                mma_bf16(sacc[2 * ntp],     ql, &kh[0]);
                mma_bf16(sacc[2 * ntp + 1], qh, &kh[2]);
                mma_bf16(sacc[2 * ntp + 1], qh, &kl[2]);
                mma_bf16(sacc[2 * ntp + 1], ql, &kh[2]);
            }
        }

        // ---- online softmax (rows r = lane/4 and r+8 of this warp's 16) ----
        float t0 = -1e30f, t1 = -1e30f;
#pragma unroll
        for (int nt = 0; nt < 16; nt++) {
            t0 = fmaxf(t0, fmaxf(sacc[nt][0], sacc[nt][1]));
            t1 = fmaxf(t1, fmaxf(sacc[nt][2], sacc[nt][3]));
        }
        t0 *= 0.125f; t1 *= 0.125f;
#pragma unroll
        for (int d = 1; d < 4; d <<= 1) {
            t0 = fmaxf(t0, __shfl_xor_sync(0xffffffffu, t0, d));
            t1 = fmaxf(t1, __shfl_xor_sync(0xffffffffu, t1, d));
        }
        float mn0 = fmaxf(m0, t0), mn1 = fmaxf(m1, t1);
        float al0 = __expf(m0 - mn0), al1 = __expf(m1 - mn1);
        m0 = mn0; m1 = mn1;
#pragma unroll
        for (int vt = 0; vt < 8; vt++) {
            oacc[vt][0] *= al0; oacc[vt][1] *= al0;
            oacc[vt][2] *= al1; oacc[vt][3] *= al1;
        }
        l0 *= al0; l1 *= al1;

        // ---- P = exp(S/8 - m), pack bf16 hi/lo fragments ----
        uint32_t phA[16], phB[16], plA[16], plB[16];
        float rs0 = 0.f, rs1 = 0.f;
#pragma unroll
        for (int nt = 0; nt < 16; nt++) {
            float p0 = __expf(fmaf(sacc[nt][0], 0.125f, -mn0));
            float p1 = __expf(fmaf(sacc[nt][1], 0.125f, -mn0));
            float p2 = __expf(fmaf(sacc[nt][2], 0.125f, -mn1));
            float p3 = __expf(fmaf(sacc[nt][3], 0.125f, -mn1));
            rs0 += p0 + p1; rs1 += p2 + p3;
            __nv_bfloat162 hA = __floats2bfloat162_rn(p0, p1);
            __nv_bfloat162 hB = __floats2bfloat162_rn(p2, p3);
            __nv_bfloat162 lA = __floats2bfloat162_rn(p0 - __bfloat162float(hA.x),
                                                      p1 - __bfloat162float(hA.y));
            __nv_bfloat162 lB = __floats2bfloat162_rn(p2 - __bfloat162float(hB.x),
                                                      p3 - __bfloat162float(hB.y));
            phA[nt] = *(uint32_t*)&hA; phB[nt] = *(uint32_t*)&hB;
            plA[nt] = *(uint32_t*)&lA; plB[nt] = *(uint32_t*)&lB;
        }
#pragma unroll
        for (int d = 1; d < 4; d <<= 1) {
            rs0 += __shfl_xor_sync(0xffffffffu, rs0, d);
            rs1 += __shfl_xor_sync(0xffffffffu, rs1, d);
        }
        l0 += rs0; l1 += rs1;

        // ---- O += P @ V (3-pass hi/lo; V via trans ldmatrix on [key][hd]) ----
#pragma unroll
        for (int kt = 0; kt < 8; kt++) {
            uint32_t pah[4] = {phA[2 * kt], phB[2 * kt], phA[2 * kt + 1], phB[2 * kt + 1]};
            uint32_t pal[4] = {plA[2 * kt], plB[2 * kt], plA[2 * kt + 1], plB[2 * kt + 1]};
#pragma unroll
            for (int vtp = 0; vtp < 4; vtp++) {
                uint32_t vh[4], vl[4];
                uint32_t vaddr = sV + (kt * 16 + ((lane >> 3) & 1) * 8 + (lane & 7)) * ARB
                               + (vtp * 16 + (lane >> 4) * 8) * 2;
                ldsm_x4t(vh, vaddr);
                ldsm_x4t(vl, vaddr + APLANE);
                mma_bf16(oacc[2 * vtp],     pah, &vh[0]);
                mma_bf16(oacc[2 * vtp],     pah, &vl[0]);
                mma_bf16(oacc[2 * vtp],     pal, &vh[0]);
                mma_bf16(oacc[2 * vtp + 1], pah, &vh[2]);
                mma_bf16(oacc[2 * vtp + 1], pah, &vl[2]);
                mma_bf16(oacc[2 * vtp + 1], pal, &vh[2]);
            }
        }

        __syncthreads();       // done reading this stage
        if (it + 2 < 16) {
            const size_t off = tok0 * TDM + (size_t)(it + 2) * 128 * TDM + h * 192;
            at_load_kv(sb + AT_KV + (it & 1) * AT_STAGE,
                       qkvhi + off + 64, qkvlo + off + 64,
                       qkvhi + off + 128, qkvlo + off + 128, tid);
        }
        CP_COMMIT();
    }

    // ---- epilogue: normalize and store ctx hi/lo planes ----
    float inv0 = 1.f / l0, inv1 = 1.f / l1;
    const size_t row0 = tok0 + i0 + wid * 16 + (lane >> 2);
    const size_t row1 = row0 + 8;
#pragma unroll
    for (int vt = 0; vt < 8; vt++) {
        int col = h * 64 + vt * 8 + (lane & 3) * 2;
        float v0 = oacc[vt][0] * inv0, v1 = oacc[vt][1] * inv0;
        float v2 = oacc[vt][2] * inv1, v3 = oacc[vt][3] * inv1;
        __nv_bfloat162 h0, l0v, h1, l1v;
        split_bf16(v0, h0.x, l0v.x); split_bf16(v1, h0.y, l0v.y);
        split_bf16(v2, h1.x, l1v.x); split_bf16(v3, h1.y, l1v.y);
        *(__nv_bfloat162*)(ctxhi + row0 * DM + col) = h0;
        *(__nv_bfloat162*)(ctxhi + row1 * DM + col) = h1;
        *(__nv_bfloat162*)(ctxlo + row0 * DM + col) = l0v;
        *(__nv_bfloat162*)(ctxlo + row1 * DM + col) = l1v;
    }
}

// --------------- LayerNorm over rows of 1024 (+ optional bf16 planes) ---------------
__global__ __launch_bounds__(256)
void ln_kernel(const float* __restrict__ x, const float* __restrict__ gamma,
               const float* __restrict__ beta, float* __restrict__ out,
               __nv_bfloat16* __restrict__ ohi, __nv_bfloat16* __restrict__ olo)
{
    __shared__ float r1[256];
    __shared__ float r2[256];
    const size_t row = blockIdx.x;
    const float* p = x + row * DM;
    const int tid = threadIdx.x;

    float4 v = *(const float4*)(p + tid * 4);
    float s  = v.x + v.y + v.z + v.w;
    float s2 = v.x * v.x + v.y * v.y + v.z * v.z + v.w * v.w;
    r1[tid] = s; r2[tid] = s2; __syncthreads();
    for (int st = 128; st > 0; st >>= 1) {
        if (tid < st) { r1[tid] += r1[tid + st]; r2[tid] += r2[tid + st]; }
        __syncthreads();
    }
    float mean = r1[0] * (1.f / DM);
    float var  = r2[0] * (1.f / DM) - mean * mean;
    float inv  = rsqrtf(var + EPS);

    float4 g = *(const float4*)(gamma + tid * 4);
    float4 b = *(const float4*)(beta + tid * 4);
    float4 o;
    o.x = (v.x - mean) * inv * g.x + b.x;
    o.y = (v.y - mean) * inv * g.y + b.y;
    o.z = (v.z - mean) * inv * g.z + b.z;
    o.w = (v.w - mean) * inv * g.w + b.w;
    *(float4*)(out + row * DM + tid * 4) = o;

    if (ohi) {
        __nv_bfloat162 h0, l0, h1, l1;
        split_bf16(o.x, h0.x, l0.x); split_bf16(o.y, h0.y, l0.y);
        split_bf16(o.z, h1.x, l1.x); split_bf16(o.w, h1.y, l1.y);
        size_t q = row * DM + tid * 4;
        *(__nv_bfloat162*)(ohi + q)     = h0;
        *(__nv_bfloat162*)(ohi + q + 2) = h1;
        *(__nv_bfloat162*)(olo + q)     = l0;
        *(__nv_bfloat162*)(olo + q + 2) = l1;
    }
}

// ---------------------------------- launch ----------------------------------
extern "C" void kernel_launch(void* const* d_in, const int* in_sizes, int n_in,
                              void* d_out, int out_size)
{
    const float* x      = (const float*)d_in[0];
    const float* W_qkv  = (const float*)d_in[1];
    const float* b_qkv  = (const float*)d_in[2];
    const float* W_o    = (const float*)d_in[3];
    const float* b_o    = (const float*)d_in[4];
    const float* gamma1 = (const float*)d_in[5];
    const float* beta1  = (const float*)d_in[6];
    const float* W1     = (const float*)d_in[7];
    const float* b1     = (const float*)d_in[8];
    const float* W2     = (const float*)d_in[9];
    const float* b2     = (const float*)d_in[10];
    const float* gamma2 = (const float*)d_in[11];
    const float* beta2  = (const float*)d_in[12];
    float* out = (float*)d_out;

    float *tmp, *hbuf;
    __nv_bfloat16 *wbf, *xbf, *qkvbf, *ctxbf, *hbf, *ffnbf;
    cudaGetSymbolAddress((void**)&tmp,    g_tmp);
    cudaGetSymbolAddress((void**)&hbuf,   g_h);
    cudaGetSymbolAddress((void**)&wbf,    g_wbf);
    cudaGetSymbolAddress((void**)&xbf,    g_xbf);
    cudaGetSymbolAddress((void**)&qkvbf,  g_qkvbf);
    cudaGetSymbolAddress((void**)&ctxbf,  g_ctxbf);
    cudaGetSymbolAddress((void**)&hbf,    g_hbf);
    cudaGetSymbolAddress((void**)&ffnbf,  g_ffnbf);

    cudaFuncSetAttribute(mma_gemm, cudaFuncAttributeMaxDynamicSharedMemorySize, MG_SMEM);
    cudaFuncSetAttribute(attn_kernel, cudaFuncAttributeMaxDynamicSharedMemorySize, AT_SMEM);

    const size_t QPL = (size_t)TOK * TDM;   // qkv plane elements
    const size_t DPL = (size_t)TOK * DM;
    const size_t FPL = (size_t)TOK * FFN;

    // 0) weight transpose+split and x split
    transpose_convert_kernel<<<dim3(TDM / 32, DM / 32), 256>>>(W_qkv, wbf + WQKV_HI, wbf + WQKV_LO, DM, TDM);
    transpose_convert_kernel<<<dim3(DM / 32, DM / 32), 256>>>(W_o, wbf + WO_HI, wbf + WO_LO, DM, DM);
    transpose_convert_kernel<<<dim3(FFN / 32, DM / 32), 256>>>(W1, wbf + W1_HI, wbf + W1_LO, DM, FFN);
    transpose_convert_kernel<<<dim3(DM / 32, FFN / 32), 256>>>(W2, wbf + W2_HI, wbf + W2_LO, FFN, DM);
    convert_kernel<<<(TOK * DM) / 1024, 256>>>(x, xbf, xbf + DPL);

    // 1) qkv = x @ W_qkv + b_qkv -> bf16 hi/lo planes
    mma_gemm<<<dim3(TDM / 128, TOK / 128), 256, MG_SMEM>>>(
        xbf, xbf + DPL, wbf + WQKV_HI, wbf + WQKV_LO,
        b_qkv, nullptr, nullptr, qkvbf, qkvbf + QPL, TOK, TDM, DM, 0);

    // 2) fused flash attention -> ctx bf16 hi/lo planes
    attn_kernel<<<dim3(S / 128, BATCH * H), 256, AT_SMEM>>>(
        qkvbf, qkvbf + QPL, ctxbf, ctxbf + DPL);

    // 3) tmp = ctx @ W_o + b_o + x
    mma_gemm<<<dim3(DM / 128, TOK / 128), 256, MG_SMEM>>>(
        ctxbf, ctxbf + DPL, wbf + WO_HI, wbf + WO_LO,
        b_o, x, tmp, nullptr, nullptr, TOK, DM, DM, 0);

    // 4) h = LN1(tmp) + planes
    ln_kernel<<<TOK, 256>>>(tmp, gamma1, beta1, hbuf, hbf, hbf + DPL);

    // 5) ffn = relu(h @ W1 + b1) -> planes only
    mma_gemm<<<dim3(FFN / 128, TOK / 128), 256, MG_SMEM>>>(
        hbf, hbf + DPL, wbf + W1_HI, wbf + W1_LO,
        b1, nullptr, nullptr, ffnbf, ffnbf + FPL, TOK, FFN, DM, 1);

    // 6) tmp = ffn @ W2 + b2 + h
    mma_gemm<<<dim3(DM / 128, TOK / 128), 256, MG_SMEM>>>(
        ffnbf, ffnbf + FPL, wbf + W2_HI, wbf + W2_LO,
        b2, hbuf, tmp, nullptr, nullptr, TOK, DM, FFN, 0);

    // 7) out = LN2(tmp)
    ln_kernel<<<TOK, 256>>>(tmp, gamma2, beta2, out, nullptr, nullptr);
}